// round 13
// baseline (speedup 1.0000x reference)
#include <cuda_runtime.h>
#include <cstdint>

// DispCorrM via banded tf32 mma.sync (HMMA) GEMM.
// R13: R9 tile geometry (256 thr, one m16-tile per warp, ~85 regs, 3 CTAs/SM
// = 24 warps/SM) + R11 load pipeline (raw-layout cp.async, K-split groups,
// fragment-time cvt.rna).
//
// out[b,d,h,w] = (1/32) * sum_c L[c,w] * R[c,w-d]   (0 if w<d)
// Per CTA (b, h, w-tile of 128): D[m,n] = sum_c A[c][m]*B[c][n]
//   A[c][m] = L[c, w0+m]      (smem rows of 128, stride 136)
//   B[c][n] = R[c, w0-64+n]   (smem rows of 192, stride 200, halo zero-filled)
//   out[d, w0+m] = D[m, m+64-d]/32
// Band: per m16-tile mt only n in [16mt, 16mt+80) needed (10 n8-tiles).

#define BB    4
#define CCH   32
#define HH    256
#define WW    512
#define DDISP 64
#define HW    ((size_t)HH * WW)

#define SA   136    // A row stride (floats); mod 32 = 8 -> fragment banks 8t+g
#define SB   200    // B row stride (floats); mod 32 = 8
#define OPAD 132    // staging row stride (floats); conflict-free band STS

__device__ __forceinline__ uint32_t f2tf32(float v) {
    uint32_t t;
    asm("cvt.rna.tf32.f32 %0, %1;" : "=r"(t) : "f"(v));
    return t;
}
__device__ __forceinline__ void cp16(uint32_t sa, const void* g, uint32_t src_bytes) {
    asm volatile("cp.async.cg.shared.global [%0], [%1], 16, %2;"
                 :: "r"(sa), "l"(g), "r"(src_bytes));
}
__device__ __forceinline__ void mma8(float* c, const uint32_t* a, uint32_t b0, uint32_t b1) {
    asm volatile(
        "mma.sync.aligned.m16n8k8.row.col.f32.tf32.tf32.f32 "
        "{%0,%1,%2,%3}, {%4,%5,%6,%7}, {%8,%9}, {%0,%1,%2,%3};"
        : "+f"(c[0]), "+f"(c[1]), "+f"(c[2]), "+f"(c[3])
        : "r"(a[0]), "r"(a[1]), "r"(a[2]), "r"(a[3]), "r"(b0), "r"(b1));
}

__global__ __launch_bounds__(256, 3)
void disp_corr_mma_kernel(const float* __restrict__ x, float* __restrict__ out) {
    __shared__ union {
        struct {
            float A[CCH * SA];       // 17.4 KB, raw fp32 L rows
            float B[CCH * SB];       // 25.6 KB, raw fp32 R rows
        } in;
        float O[DDISP * OPAD];       // 33.8 KB staging (aliased after mainloop)
    } sm;

    const int tid  = threadIdx.x;
    const int lane = tid & 31;
    const int warp = tid >> 5;          // 0..7 (= m16-tile index)
    const int g    = lane >> 2;         // 0..7
    const int t    = lane & 3;          // 0..3
    const int tile = blockIdx.x;        // 0..3
    const int h    = blockIdx.y;
    const int b    = blockIdx.z;
    const int w0   = tile * 128;

    const float* Lg = x + (((size_t)b * 2 * CCH) * HH + h) * WW + w0;
    const float* Rg = x + (((size_t)b * 2 * CCH + CCH) * HH + h) * WW;

    const uint32_t abase = (uint32_t)__cvta_generic_to_shared(sm.in.A);
    const uint32_t bbase = (uint32_t)__cvta_generic_to_shared(sm.in.B);

    // ---- K-chunk loader: channels [c0, c0+16). A: 512 granules, B: 768. ----
    auto load_half = [&](int c0) {
        #pragma unroll
        for (int k = 0; k < 2; k++) {                 // A: 512 granules / 256 thr
            int idx = k * 256 + tid;
            int c = c0 + (idx >> 5), q = idx & 31;
            cp16(abase + (c * SA + 4 * q) * 4, Lg + (size_t)c * HW + 4 * q, 16);
        }
        #pragma unroll
        for (int k = 0; k < 3; k++) {                 // B: 768 granules / 256 thr
            int idx = k * 256 + tid;
            int c = c0 + idx / 48, q = idx % 48;
            int wg = w0 - 64 + 4 * q;                 // granule-aligned: all-in or all-out
            const float* src = Rg + (size_t)c * HW + (wg >= 0 ? wg : 0);
            cp16(bbase + (c * SB + 4 * q) * 4, src, wg >= 0 ? 16u : 0u);
        }
        asm volatile("cp.async.commit_group;");
    };

    load_half(0);    // group 0: channels 0-15  (covers ks 0,1)
    load_half(16);   // group 1: channels 16-31 (covers ks 2,3)

    // ---- Mainloop: warp owns m16-tile 'warp'; n_base = 16*warp + 8j, j=0..9 ----
    const float* ap = &sm.in.A[t * SA + 16 * warp + g];
    const float* bp = &sm.in.B[t * SB + 16 * warp + g];

    float C[10][4];
    #pragma unroll
    for (int j = 0; j < 10; j++)
        #pragma unroll
        for (int r = 0; r < 4; r++) C[j][r] = 0.f;

    asm volatile("cp.async.wait_group 1;");   // chunk 0 landed
    __syncthreads();

    #pragma unroll
    for (int ks = 0; ks < 4; ks++) {
        if (ks == 2) {
            asm volatile("cp.async.wait_group 0;");   // chunk 1 landed
            __syncthreads();
        }
        const float* a = ap + 8 * ks * SA;
        uint32_t af[4];
        af[0] = f2tf32(a[0]);           af[1] = f2tf32(a[8]);
        af[2] = f2tf32(a[4 * SA]);      af[3] = f2tf32(a[4 * SA + 8]);

        const float* bb = bp + 8 * ks * SB;
        #pragma unroll
        for (int j = 0; j < 10; j++) {
            uint32_t b0 = f2tf32(bb[8 * j]);
            uint32_t b1 = f2tf32(bb[4 * SB + 8 * j]);
            mma8(C[j], af, b0, b1);
        }
    }

    __syncthreads();   // operand LDS done before aliasing smem as staging

    // ---- Band extraction: d = m + 64 - n = g - 8j - 2t + 64 (+offsets) ----
    const float inv_c = 1.0f / 32.0f;
    {
        const int mbase = 16 * warp + g;
        #pragma unroll
        for (int j = 0; j < 10; j++) {
            const int dbase = g + 64 - 8 * j - 2 * t;
            if ((unsigned)dbase       < 64u) sm.O[dbase       * OPAD + mbase]     = C[j][0] * inv_c;
            if ((unsigned)(dbase - 1) < 64u) sm.O[(dbase - 1) * OPAD + mbase]     = C[j][1] * inv_c;
            if ((unsigned)(dbase + 8) < 64u) sm.O[(dbase + 8) * OPAD + mbase + 8] = C[j][2] * inv_c;
            if ((unsigned)(dbase + 7) < 64u) sm.O[(dbase + 7) * OPAD + mbase + 8] = C[j][3] * inv_c;
        }
    }
    __syncthreads();

    // ---- Coalesced store: warp handles d = 8i + warp, float4 per lane ----
    float* op = out + (((size_t)b * DDISP) * HH + h) * WW + w0;
    #pragma unroll
    for (int i = 0; i < 8; i++) {
        const int d = 8 * i + warp;
        float4 v = *(const float4*)&sm.O[d * OPAD + 4 * lane];
        *(float4*)(op + (size_t)d * HW + 4 * lane) = v;
    }
}

extern "C" void kernel_launch(void* const* d_in, const int* in_sizes, int n_in,
                              void* d_out, int out_size) {
    const float* x = (const float*)d_in[0];
    float* out = (float*)d_out;
    dim3 grid(WW / 128, HH, BB);   // (4, 256, 4) = 4096 blocks
    disp_corr_mma_kernel<<<grid, 256>>>(x, out);
}

// round 15
// speedup vs baseline: 1.0975x; 1.0975x over previous
#include <cuda_runtime.h>
#include <cstdint>

// DispCorrM via banded tf32 mma.sync (HMMA) GEMM.
// R14: R11 skeleton (128 thr, warp owns m16-tiles {2w,2w+1}, 4 CTAs/SM) with
// a 4-deep K-split cp.async pipeline: 8-channel groups, progressive
// wait_group 3/2/1/0 so compute starts after only 10.7 KB has landed and the
// remaining 32 KB streams in under the MMAs.
//
// out[b,d,h,w] = (1/32) * sum_c L[c,w] * R[c,w-d]   (0 if w<d)
// Per CTA (b, h, w-tile of 128): D[m,n] = sum_c A[c][m]*B[c][n]
//   A[c][m] = L[c, w0+m]      (smem rows of 128, stride 136: 8t+g banks)
//   B[c][n] = R[c, w0-64+n]   (smem rows of 192, stride 200, halo zero-filled)
//   out[d, w0+m] = D[m, m+64-d]/32
// Band: per m16-tile mt only n in [16mt, 16mt+80) needed (10 n8-tiles).

#define BB    4
#define CCH   32
#define HH    256
#define WW    512
#define DDISP 64
#define HW    ((size_t)HH * WW)

#define SA   136    // A row stride (floats); mod 32 = 8 -> conflict-free frags
#define SB   200    // B row stride (floats); mod 32 = 8
#define OPAD 132    // staging row stride (floats); conflict-free band STS

__device__ __forceinline__ uint32_t f2tf32(float v) {
    uint32_t t;
    asm("cvt.rna.tf32.f32 %0, %1;" : "=r"(t) : "f"(v));
    return t;
}
__device__ __forceinline__ void cp16(uint32_t sa, const void* g, uint32_t src_bytes) {
    asm volatile("cp.async.cg.shared.global [%0], [%1], 16, %2;"
                 :: "r"(sa), "l"(g), "r"(src_bytes));
}
template <int N>
__device__ __forceinline__ void cp_wait() {
    asm volatile("cp.async.wait_group %0;" :: "n"(N));
}
__device__ __forceinline__ void mma8(float* c, const uint32_t* a, uint32_t b0, uint32_t b1) {
    asm volatile(
        "mma.sync.aligned.m16n8k8.row.col.f32.tf32.tf32.f32 "
        "{%0,%1,%2,%3}, {%4,%5,%6,%7}, {%8,%9}, {%0,%1,%2,%3};"
        : "+f"(c[0]), "+f"(c[1]), "+f"(c[2]), "+f"(c[3])
        : "r"(a[0]), "r"(a[1]), "r"(a[2]), "r"(a[3]), "r"(b0), "r"(b1));
}

__global__ __launch_bounds__(128, 4)
void disp_corr_mma_kernel(const float* __restrict__ x, float* __restrict__ out) {
    __shared__ union {
        struct {
            float A[CCH * SA];       // 17.4 KB, raw fp32 L rows
            float B[CCH * SB];       // 25.6 KB, raw fp32 R rows
        } in;
        float O[DDISP * OPAD];       // 33.8 KB staging (aliased after mainloop)
    } sm;

    const int tid  = threadIdx.x;
    const int lane = tid & 31;
    const int warp = tid >> 5;          // 0..3
    const int g    = lane >> 2;         // 0..7
    const int t    = lane & 3;          // 0..3
    const int tile = blockIdx.x;        // 0..3
    const int h    = blockIdx.y;
    const int b    = blockIdx.z;
    const int w0   = tile * 128;

    const float* Lg = x + (((size_t)b * 2 * CCH) * HH + h) * WW + w0;
    const float* Rg = x + (((size_t)b * 2 * CCH + CCH) * HH + h) * WW;

    const uint32_t abase = (uint32_t)__cvta_generic_to_shared(sm.in.A);
    const uint32_t bbase = (uint32_t)__cvta_generic_to_shared(sm.in.B);

    // ---- K-quarter loader: channels [c0, c0+8). A: 256 granules, B: 384. ----
    auto load_q = [&](int c0) {
        #pragma unroll
        for (int k = 0; k < 2; k++) {                 // A: 256 granules / 128 thr
            int idx = k * 128 + tid;
            int c = c0 + (idx >> 5), q = idx & 31;
            cp16(abase + (c * SA + 4 * q) * 4, Lg + (size_t)c * HW + 4 * q, 16);
        }
        #pragma unroll
        for (int k = 0; k < 3; k++) {                 // B: 384 granules / 128 thr
            int idx = k * 128 + tid;
            int c = c0 + idx / 48, q = idx % 48;
            int wg = w0 - 64 + 4 * q;                 // granule-aligned: all-in or all-out
            const float* src = Rg + (size_t)c * HW + (wg >= 0 ? wg : 0);
            cp16(bbase + (c * SB + 4 * q) * 4, src, wg >= 0 ? 16u : 0u);
        }
        asm volatile("cp.async.commit_group;");
    };

    load_q(0);      // group 0: channels 0-7   (ks 0)
    load_q(8);      // group 1: channels 8-15  (ks 1)
    load_q(16);     // group 2: channels 16-23 (ks 2)
    load_q(24);     // group 3: channels 24-31 (ks 3)

    // ---- Mainloop: warp owns m16-tiles {2w, 2w+1}; B tiles j=0..11 shared ----
    const float* ap = &sm.in.A[t * SA + 32 * warp + g];
    const float* bp = &sm.in.B[t * SB + 32 * warp + g];

    float C0[10][4], C1[10][4];
    #pragma unroll
    for (int j = 0; j < 10; j++)
        #pragma unroll
        for (int r = 0; r < 4; r++) { C0[j][r] = 0.f; C1[j][r] = 0.f; }

    #pragma unroll
    for (int ks = 0; ks < 4; ks++) {
        // progressive drain: group ks landed, later groups still in flight
        if (ks == 0) cp_wait<3>();
        if (ks == 1) cp_wait<2>();
        if (ks == 2) cp_wait<1>();
        if (ks == 3) cp_wait<0>();
        __syncthreads();

        const float* a = ap + 8 * ks * SA;
        uint32_t a0[4], a1[4];
        a0[0] = f2tf32(a[0]);               a0[1] = f2tf32(a[8]);
        a0[2] = f2tf32(a[4 * SA]);          a0[3] = f2tf32(a[4 * SA + 8]);
        a1[0] = f2tf32(a[16]);              a1[1] = f2tf32(a[24]);
        a1[2] = f2tf32(a[4 * SA + 16]);     a1[3] = f2tf32(a[4 * SA + 24]);

        const float* bb = bp + 8 * ks * SB;
        #pragma unroll
        for (int j = 0; j < 12; j++) {
            uint32_t b0 = f2tf32(bb[8 * j]);
            uint32_t b1 = f2tf32(bb[4 * SB + 8 * j]);
            if (j < 10) mma8(C0[j], a0, b0, b1);
            if (j >= 2) mma8(C1[j - 2], a1, b0, b1);
        }
    }

    __syncthreads();   // operand LDS done before aliasing smem as staging

    // ---- Band extraction: d = m + 64 - n ----
    const float inv_c = 1.0f / 32.0f;
    #pragma unroll
    for (int half = 0; half < 2; half++) {
        const int mbase = 32 * warp + 16 * half + g;
        #pragma unroll
        for (int j = 0; j < 10; j++) {
            const float* Cr = half ? C1[j] : C0[j];
            const int dbase = g + 64 - 8 * j - 2 * t;
            if ((unsigned)dbase       < 64u) sm.O[dbase       * OPAD + mbase]     = Cr[0] * inv_c;
            if ((unsigned)(dbase - 1) < 64u) sm.O[(dbase - 1) * OPAD + mbase]     = Cr[1] * inv_c;
            if ((unsigned)(dbase + 8) < 64u) sm.O[(dbase + 8) * OPAD + mbase + 8] = Cr[2] * inv_c;
            if ((unsigned)(dbase + 7) < 64u) sm.O[(dbase + 7) * OPAD + mbase + 8] = Cr[3] * inv_c;
        }
    }
    __syncthreads();

    // ---- Coalesced store: warp handles d = warp + 4i, float4 per lane ----
    float* op = out + (((size_t)b * DDISP) * HH + h) * WW + w0;
    #pragma unroll
    for (int i = 0; i < 16; i++) {
        const int d = 4 * i + warp;
        float4 v = *(const float4*)&sm.O[d * OPAD + 4 * lane];
        *(float4*)(op + (size_t)d * HW + 4 * lane) = v;
    }
}

extern "C" void kernel_launch(void* const* d_in, const int* in_sizes, int n_in,
                              void* d_out, int out_size) {
    const float* x = (const float*)d_in[0];
    float* out = (float*)d_out;
    dim3 grid(WW / 128, HH, BB);   // (4, 256, 4) = 4096 blocks
    disp_corr_mma_kernel<<<grid, 128>>>(x, out);
}